// round 7
// baseline (speedup 1.0000x reference)
#include <cuda_runtime.h>
#include <cuda_fp16.h>
#include <cstdint>

#define N_MAX 50000
#define E_MAX 800000

// ---------------- scratch (__device__ globals; no allocs allowed) ----------
__device__ int      g_deg_in[N_MAX];
__device__ int      g_deg_out[N_MAX];
__device__ int      g_row_start[N_MAX + 1];
__device__ int      g_cursor[N_MAX];
__device__ int      g_csr_src[E_MAX];
__device__ float    g_norm_src[N_MAX];
__device__ uint2    g_h16[(size_t)N_MAX * 32];    // fp16 x*norm_src (4 halves each)
__device__ uint2    g_aggh[(size_t)N_MAX * 32];   // fp16 aggregated rows

__device__ __forceinline__ void mma_f16(float c[4], uint32_t a0, uint32_t a1,
                                        uint32_t a2, uint32_t a3,
                                        uint32_t b0, uint32_t b1) {
    asm volatile(
        "mma.sync.aligned.m16n8k16.row.col.f32.f16.f16.f32 "
        "{%0,%1,%2,%3}, {%4,%5,%6,%7}, {%8,%9}, {%0,%1,%2,%3};"
        : "+f"(c[0]), "+f"(c[1]), "+f"(c[2]), "+f"(c[3])
        : "r"(a0), "r"(a1), "r"(a2), "r"(a3), "r"(b0), "r"(b1));
}

// ---------------- prep ------------------------------------------------------
__global__ void k_init(int n4) {
    int i = blockIdx.x * blockDim.x + threadIdx.x;
    int4 z = make_int4(0, 0, 0, 0);
    if (i < n4) {
        reinterpret_cast<int4*>(g_deg_in)[i] = z;
        reinterpret_cast<int4*>(g_deg_out)[i] = z;
        reinterpret_cast<int4*>(g_cursor)[i] = z;
    }
}

__global__ void k_count(const int* __restrict__ ei, int e4, int e) {
    int i = blockIdx.x * blockDim.x + threadIdx.x;
    if (i < e4) {
        int4 s = reinterpret_cast<const int4*>(ei)[i];
        int4 d = reinterpret_cast<const int4*>(ei + e)[i];
        atomicAdd(&g_deg_out[s.x], 1); atomicAdd(&g_deg_out[s.y], 1);
        atomicAdd(&g_deg_out[s.z], 1); atomicAdd(&g_deg_out[s.w], 1);
        atomicAdd(&g_deg_in[d.x], 1);  atomicAdd(&g_deg_in[d.y], 1);
        atomicAdd(&g_deg_in[d.z], 1);  atomicAdd(&g_deg_in[d.w], 1);
    }
}

__global__ void k_scan(int n) {
    __shared__ int part[1024];
    int t = threadIdx.x;
    int chunk = (n + 1023) / 1024;
    int beg = min(t * chunk, n);
    int end = min(beg + chunk, n);
    int own = 0;
    for (int i = beg; i < end; ++i) own += g_deg_in[i];
    part[t] = own;
    __syncthreads();
#pragma unroll
    for (int off = 1; off < 1024; off <<= 1) {
        int v = (t >= off) ? part[t - off] : 0;
        __syncthreads();
        part[t] += v;
        __syncthreads();
    }
    if (t == 1023) g_row_start[n] = part[1023];
    int run = part[t] - own;
    for (int i = beg; i < end; ++i) {
        g_row_start[i] = run;
        run += g_deg_in[i];
        g_norm_src[i] = rsqrtf(fmaxf((float)g_deg_out[i], 1.0f));
    }
}

__global__ void k_fill_half(const int* __restrict__ ei, const float* __restrict__ x,
                            int e, int n) {
    int i = blockIdx.x * blockDim.x + threadIdx.x;
    if (i < e) {
        int s = ei[i];
        int d = ei[e + i];
        int pos = atomicAdd(&g_cursor[d], 1);
        g_csr_src[g_row_start[d] + pos] = s;
    }
    int cvt_total = n * 32;
    if (i < cvt_total) {
        int node = i >> 5;
        float nm = g_norm_src[node];
        float4 v = reinterpret_cast<const float4*>(x)[i];
        __half2 h0 = __floats2half2_rn(v.x * nm, v.y * nm);
        __half2 h1 = __floats2half2_rn(v.z * nm, v.w * nm);
        uint2 o;
        o.x = *(uint32_t*)&h0;
        o.y = *(uint32_t*)&h1;
        g_h16[i] = o;
    }
}

// ---------------- aggregation: one warp per destination node, MLP 8 ---------
__global__ __launch_bounds__(256)
void k_agg(int n) {
    int warp = (blockIdx.x * blockDim.x + threadIdx.x) >> 5;
    int lane = threadIdx.x & 31;
    if (warp >= n) return;

    int beg = g_row_start[warp];
    int end = g_row_start[warp + 1];
    int deg = end - beg;

    float ax = 0.f, ay = 0.f, az = 0.f, aw = 0.f;

    int idx = beg;
    for (; idx + 8 <= end; idx += 8) {
        int s[8];
#pragma unroll
        for (int j = 0; j < 8; ++j) s[j] = g_csr_src[idx + j];
        uint2 v[8];
#pragma unroll
        for (int j = 0; j < 8; ++j) v[j] = g_h16[(size_t)s[j] * 32 + lane];
#pragma unroll
        for (int j = 0; j < 8; ++j) {
            float2 f0 = __half22float2(*(__half2*)&v[j].x);
            float2 f1 = __half22float2(*(__half2*)&v[j].y);
            ax += f0.x; ay += f0.y; az += f1.x; aw += f1.y;
        }
    }
    for (; idx < end; ++idx) {
        int s0 = g_csr_src[idx];
        uint2 v0 = g_h16[(size_t)s0 * 32 + lane];
        float2 f0 = __half22float2(*(__half2*)&v0.x);
        float2 f1 = __half22float2(*(__half2*)&v0.y);
        ax += f0.x; ay += f0.y; az += f1.x; aw += f1.y;
    }

    float nd = rsqrtf(fmaxf((float)deg, 1.0f));
    __half2 h0 = __floats2half2_rn(ax * nd, ay * nd);
    __half2 h1 = __floats2half2_rn(az * nd, aw * nd);
    uint2 o;
    o.x = *(uint32_t*)&h0;
    o.y = *(uint32_t*)&h1;
    g_aggh[(size_t)warp * 32 + lane] = o;
}

// ---------------- GEMM: 64-row tiles, warp col-split, fp16 HMMA -------------
// smem: bias 512B | A: 64 rows x 64 words, XOR-rotated (16KB) | B frags (32KB)
// total ~48.5KB -> 4 CTAs/SM
#define SM_BIAS  0
#define SM_A     512
#define SM_BF    (512 + 64 * 256)
#define SM_TOTAL (SM_BF + 16 * 8 * 32 * 8)

__global__ __launch_bounds__(256, 4)
void k_gemm(const float* __restrict__ Wm, const float* __restrict__ bias,
            float* __restrict__ out, int n) {
    extern __shared__ char smem[];
    float*    sBias = (float*)(smem + SM_BIAS);
    uint32_t* sA    = (uint32_t*)(smem + SM_A);
    uint2*    sBf   = (uint2*)(smem + SM_BF);

    int tid = threadIdx.x;
    int wid = tid >> 5;
    int lid = tid & 31;
    int rowBase = blockIdx.x * 64;

    if (tid < 128) sBias[tid] = bias[tid];

    // stage W (k-major [k][n]) into m16n8k16 B-fragment layout (B = W^T col-major)
#pragma unroll
    for (int i = 0; i < 64; ++i) {
        int idx = tid + i * 256;
        int k = idx >> 7;
        int nn = idx & 127;
        int nt = nn >> 3, ks = k >> 4;
        int klo = k & 15;
        int lane = ((nn & 7) << 2) | ((klo & 7) >> 1);
        int reg = klo >> 3;
        int hs = klo & 1;
        __half hv = __float2half_rn(Wm[idx]);
        ((__half*)&sBf[(nt * 8 + ks) * 32 + lane])[reg * 2 + hs] = hv;
    }

    // stage A: 64 rows x 16 uint4 chunks, word-rotated by 4*row (conflict-free)
#pragma unroll
    for (int i = 0; i < 4; ++i) {
        int fid = tid + i * 256;          // 0..1023
        int r = fid >> 4;                 // 0..63
        int cq = fid & 15;                // chunk (4 words = 8 halves)
        int grow = rowBase + r;
        uint4 v = make_uint4(0u, 0u, 0u, 0u);
        if (grow < n)
            v = reinterpret_cast<const uint4*>(&g_aggh[(size_t)grow * 32])[cq];
        int w = (cq * 4 + r * 4) & 63;    // rotation preserves 16B alignment
        *reinterpret_cast<uint4*>(&sA[r * 64 + w]) = v;
    }
    __syncthreads();

    // warp w: rows [(w>>1)*16, +16), cols [(w&1)*64, +64)
    float acc[8][4];
#pragma unroll
    for (int nt = 0; nt < 8; ++nt)
#pragma unroll
        for (int q = 0; q < 4; ++q) acc[nt][q] = 0.f;

    int mstrip = (wid >> 1) * 16;
    int colH = (wid & 1) * 8;             // nt group offset
    int m0 = mstrip + (lid >> 2);         // rows m0, m0+8

#pragma unroll
    for (int ks = 0; ks < 8; ++ks) {
        int wbase = ks * 8 + (lid & 3);   // word index before rotation
        uint32_t a0 = sA[m0 * 64 + ((wbase + m0 * 4) & 63)];
        uint32_t a1 = sA[(m0 + 8) * 64 + ((wbase + (m0 + 8) * 4) & 63)];
        uint32_t a2 = sA[m0 * 64 + ((wbase + 4 + m0 * 4) & 63)];
        uint32_t a3 = sA[(m0 + 8) * 64 + ((wbase + 4 + (m0 + 8) * 4) & 63)];
#pragma unroll
        for (int nt = 0; nt < 8; ++nt) {
            uint2 b = sBf[((colH + nt) * 8 + ks) * 32 + lid];
            mma_f16(acc[nt], a0, a1, a2, a3, b.x, b.y);
        }
    }

    // epilogue: bias + relu
    int rA = rowBase + m0;
    int rB = rA + 8;
#pragma unroll
    for (int nt = 0; nt < 8; ++nt) {
        int col = (colH + nt) * 8 + (lid & 3) * 2;
        float b0 = sBias[col], b1 = sBias[col + 1];
        if (rA < n) {
            float2 v;
            v.x = fmaxf(acc[nt][0] + b0, 0.f);
            v.y = fmaxf(acc[nt][1] + b1, 0.f);
            *(float2*)&out[(size_t)rA * 128 + col] = v;
        }
        if (rB < n) {
            float2 v;
            v.x = fmaxf(acc[nt][2] + b0, 0.f);
            v.y = fmaxf(acc[nt][3] + b1, 0.f);
            *(float2*)&out[(size_t)rB * 128 + col] = v;
        }
    }
}

// ---------------- launch ----------------------------------------------------
extern "C" void kernel_launch(void* const* d_in, const int* in_sizes, int n_in,
                              void* d_out, int out_size) {
    const float* x    = (const float*)d_in[0];
    const int*   ei   = (const int*)d_in[1];
    const float* Wm   = (const float*)d_in[2];
    const float* bias = (const float*)d_in[3];
    float* out = (float*)d_out;

    int n = in_sizes[0] / 128;   // 50000
    int e = in_sizes[1] / 2;     // 800000
    int n4 = (n + 3) / 4;
    int e4 = e / 4;

    cudaFuncSetAttribute(k_gemm, cudaFuncAttributeMaxDynamicSharedMemorySize, SM_TOTAL);
    cudaFuncSetAttribute(k_gemm, cudaFuncAttributePreferredSharedMemoryCarveout, 100);

    k_init<<<(n4 + 255) / 256, 256>>>(n4);
    k_count<<<(e4 + 255) / 256, 256>>>(ei, e4, e);
    k_scan<<<1, 1024>>>(n);
    int fh_threads = (n * 32 > e) ? n * 32 : e;
    k_fill_half<<<(fh_threads + 255) / 256, 256>>>(ei, x, e, n);
    k_agg<<<(n * 32 + 255) / 256, 256>>>(n);
    k_gemm<<<(n + 63) / 64, 256, SM_TOTAL>>>(Wm, bias, out, n);
}

// round 8
// speedup vs baseline: 1.1001x; 1.1001x over previous
#include <cuda_runtime.h>
#include <cuda_fp16.h>
#include <cstdint>

#define N_MAX 50000
#define E_MAX 800000

// ---------------- scratch (__device__ globals; zero-initialized at load) ----
__device__ int      g_deg_in[N_MAX];     // zeroed by k_init at END of prior call
__device__ int      g_deg_out[N_MAX];
__device__ int      g_cursor[N_MAX];
__device__ int      g_row_start[N_MAX + 1];
__device__ int      g_csr_src[E_MAX];
__device__ float    g_norm_src[N_MAX];
__device__ uint2    g_h16[(size_t)N_MAX * 32];    // fp16 x*norm_src
__device__ uint2    g_aggh[(size_t)N_MAX * 32];   // fp16 aggregated rows
__device__ uint32_t g_wfrag[8192];                // W in HMMA B-fragment layout

__device__ __forceinline__ void mma_f16(float c[4], uint32_t a0, uint32_t a1,
                                        uint32_t a2, uint32_t a3,
                                        uint32_t b0, uint32_t b1) {
    asm volatile(
        "mma.sync.aligned.m16n8k16.row.col.f32.f16.f16.f32 "
        "{%0,%1,%2,%3}, {%4,%5,%6,%7}, {%8,%9}, {%0,%1,%2,%3};"
        : "+f"(c[0]), "+f"(c[1]), "+f"(c[2]), "+f"(c[3])
        : "r"(a0), "r"(a1), "r"(a2), "r"(a3), "r"(b0), "r"(b1));
}

// ---------------- launch 0: degree count (counters pre-zeroed) --------------
__global__ void k_count(const int* __restrict__ ei, int e) {
    int i = blockIdx.x * blockDim.x + threadIdx.x;
    if (i < e) {
        atomicAdd(&g_deg_out[ei[i]], 1);
        atomicAdd(&g_deg_in[ei[e + i]], 1);
    }
}

// ---------------- launch 1: scan + norms ------------------------------------
__global__ void k_scan(int n) {
    __shared__ int part[1024];
    int t = threadIdx.x;
    int chunk = (n + 1023) / 1024;
    int beg = min(t * chunk, n);
    int end = min(beg + chunk, n);
    int own = 0;
    for (int i = beg; i < end; ++i) own += g_deg_in[i];
    part[t] = own;
    __syncthreads();
#pragma unroll
    for (int off = 1; off < 1024; off <<= 1) {
        int v = (t >= off) ? part[t - off] : 0;
        __syncthreads();
        part[t] += v;
        __syncthreads();
    }
    if (t == 1023) g_row_start[n] = part[1023];
    int run = part[t] - own;
    for (int i = beg; i < end; ++i) {
        g_row_start[i] = run;
        run += g_deg_in[i];
        g_norm_src[i] = rsqrtf(fmaxf((float)g_deg_out[i], 1.0f));
    }
}

// ---------------- launch 2: CSR fill + fp16 x conversion + W frag conv ------
__global__ void k_fill_half(const int* __restrict__ ei, const float* __restrict__ x,
                            const float* __restrict__ Wm, int e, int n) {
    int i = blockIdx.x * blockDim.x + threadIdx.x;
    if (i < e) {
        int s = ei[i];
        int d = ei[e + i];
        int pos = atomicAdd(&g_cursor[d], 1);
        g_csr_src[g_row_start[d] + pos] = s;
    }
    int cvt_total = n * 32;
    if (i < cvt_total) {
        int node = i >> 5;
        float nm = g_norm_src[node];
        float4 v = reinterpret_cast<const float4*>(x)[i];
        __half2 h0 = __floats2half2_rn(v.x * nm, v.y * nm);
        __half2 h1 = __floats2half2_rn(v.z * nm, v.w * nm);
        uint2 o;
        o.x = *(uint32_t*)&h0;
        o.y = *(uint32_t*)&h1;
        g_h16[i] = o;
    }
    // W -> m16n8k16 B-fragment image: u = (nt*8+ks)*64 + lane*2 + reg
    if (i < 8192) {
        int u = i;
        int reg  = u & 1;
        int lane = (u >> 1) & 31;
        int grp  = u >> 6;              // nt*8+ks
        int ks   = grp & 7;
        int nt   = grp >> 3;
        int nn   = nt * 8 + (lane >> 2);
        int klo  = (lane & 3) * 2 + reg * 8;
        int k    = ks * 16 + klo;
        __half2 h = __floats2half2_rn(Wm[k * 128 + nn], Wm[(k + 1) * 128 + nn]);
        g_wfrag[u] = *(uint32_t*)&h;
    }
}

// ---------------- launch 3 (PROFILED): aggregation, warp per node -----------
__global__ __launch_bounds__(256)
void k_agg(int n) {
    int warp = (blockIdx.x * blockDim.x + threadIdx.x) >> 5;
    int lane = threadIdx.x & 31;
    if (warp >= n) return;

    int beg = g_row_start[warp];
    int end = g_row_start[warp + 1];
    int deg = end - beg;

    float ax = 0.f, ay = 0.f, az = 0.f, aw = 0.f;

    int idx = beg;
    for (; idx + 4 <= end; idx += 4) {
        int s0 = g_csr_src[idx],     s1 = g_csr_src[idx + 1];
        int s2 = g_csr_src[idx + 2], s3 = g_csr_src[idx + 3];
        uint2 v0 = g_h16[(size_t)s0 * 32 + lane];
        uint2 v1 = g_h16[(size_t)s1 * 32 + lane];
        uint2 v2 = g_h16[(size_t)s2 * 32 + lane];
        uint2 v3 = g_h16[(size_t)s3 * 32 + lane];
        float2 f;
        f = __half22float2(*(__half2*)&v0.x); ax += f.x; ay += f.y;
        f = __half22float2(*(__half2*)&v0.y); az += f.x; aw += f.y;
        f = __half22float2(*(__half2*)&v1.x); ax += f.x; ay += f.y;
        f = __half22float2(*(__half2*)&v1.y); az += f.x; aw += f.y;
        f = __half22float2(*(__half2*)&v2.x); ax += f.x; ay += f.y;
        f = __half22float2(*(__half2*)&v2.y); az += f.x; aw += f.y;
        f = __half22float2(*(__half2*)&v3.x); ax += f.x; ay += f.y;
        f = __half22float2(*(__half2*)&v3.y); az += f.x; aw += f.y;
    }
    for (; idx < end; ++idx) {
        int s0 = g_csr_src[idx];
        uint2 v0 = g_h16[(size_t)s0 * 32 + lane];
        float2 f;
        f = __half22float2(*(__half2*)&v0.x); ax += f.x; ay += f.y;
        f = __half22float2(*(__half2*)&v0.y); az += f.x; aw += f.y;
    }

    float nd = rsqrtf(fmaxf((float)deg, 1.0f));
    __half2 h0 = __floats2half2_rn(ax * nd, ay * nd);
    __half2 h1 = __floats2half2_rn(az * nd, aw * nd);
    uint2 o;
    o.x = *(uint32_t*)&h0;
    o.y = *(uint32_t*)&h1;
    g_aggh[(size_t)warp * 32 + lane] = o;
}

// ---------------- launch 4: GEMM (R6 geometry, cheap B staging) -------------
// smem: bias 512B | A tile 128 x 136 halves (34KB) | B frags 32KB => ~67KB
#define A_PITCH_H 136
#define SM_BIAS   0
#define SM_A      512
#define SM_BF     (512 + 128 * A_PITCH_H * 2)
#define SM_TOTAL  (SM_BF + 16 * 8 * 32 * 8)

__global__ __launch_bounds__(256, 2)
void k_gemm(const float* __restrict__ bias, float* __restrict__ out, int n) {
    extern __shared__ char smem[];
    float*    sBias = (float*)(smem + SM_BIAS);
    __half*   sA    = (__half*)(smem + SM_A);
    uint2*    sBf   = (uint2*)(smem + SM_BF);

    int tid = threadIdx.x;
    int wid = tid >> 5;
    int lid = tid & 31;
    int rowBase = blockIdx.x * 128;

    if (tid < 128) sBias[tid] = bias[tid];

    // stage B fragments: coalesced uint4 copy of pre-converted image (32KB)
#pragma unroll
    for (int i = 0; i < 8; ++i) {
        int u4 = tid + i * 256;           // 0..2047
        reinterpret_cast<uint4*>(sBf)[u4] =
            reinterpret_cast<const uint4*>(g_wfrag)[u4];
    }

    // stage A tile coalesced: 128 rows x 128 halves from g_aggh
#pragma unroll
    for (int i = 0; i < 8; ++i) {
        int fid = tid + i * 256;          // 0..2047
        int r = fid >> 4;                 // 0..127
        int cq = fid & 15;                // 16B chunk (8 halves)
        int grow = rowBase + r;
        uint4 v = make_uint4(0u, 0u, 0u, 0u);
        if (grow < n)
            v = reinterpret_cast<const uint4*>(&g_aggh[(size_t)grow * 32])[cq];
        *reinterpret_cast<uint4*>(&sA[r * A_PITCH_H + cq * 8]) = v;
    }
    __syncthreads();

    float acc[16][4];
#pragma unroll
    for (int nt = 0; nt < 16; ++nt)
#pragma unroll
        for (int q = 0; q < 4; ++q) acc[nt][q] = 0.f;

    int m0 = wid * 16 + (lid >> 2);       // fragment rows m0, m0+8
#pragma unroll
    for (int ks = 0; ks < 8; ++ks) {
        int k0 = ks * 16 + (lid & 3) * 2;
        uint32_t a0 = *(const uint32_t*)&sA[m0 * A_PITCH_H + k0];
        uint32_t a1 = *(const uint32_t*)&sA[(m0 + 8) * A_PITCH_H + k0];
        uint32_t a2 = *(const uint32_t*)&sA[m0 * A_PITCH_H + k0 + 8];
        uint32_t a3 = *(const uint32_t*)&sA[(m0 + 8) * A_PITCH_H + k0 + 8];
#pragma unroll
        for (int nt = 0; nt < 16; ++nt) {
            uint2 b = sBf[(nt * 8 + ks) * 32 + lid];
            mma_f16(acc[nt], a0, a1, a2, a3, b.x, b.y);
        }
    }

    int rA = rowBase + m0;
    int rB = rA + 8;
#pragma unroll
    for (int nt = 0; nt < 16; ++nt) {
        int col = nt * 8 + (lid & 3) * 2;
        float b0 = sBias[col], b1 = sBias[col + 1];
        if (rA < n) {
            float2 v;
            v.x = fmaxf(acc[nt][0] + b0, 0.f);
            v.y = fmaxf(acc[nt][1] + b1, 0.f);
            *(float2*)&out[(size_t)rA * 128 + col] = v;
        }
        if (rB < n) {
            float2 v;
            v.x = fmaxf(acc[nt][2] + b0, 0.f);
            v.y = fmaxf(acc[nt][3] + b1, 0.f);
            *(float2*)&out[(size_t)rB * 128 + col] = v;
        }
    }
}

// ---------------- launch 5: zero counters for the NEXT call -----------------
__global__ void k_init(int n4) {
    int i = blockIdx.x * blockDim.x + threadIdx.x;
    int4 z = make_int4(0, 0, 0, 0);
    if (i < n4) {
        reinterpret_cast<int4*>(g_deg_in)[i] = z;
        reinterpret_cast<int4*>(g_deg_out)[i] = z;
        reinterpret_cast<int4*>(g_cursor)[i] = z;
    }
}

// ---------------- launch ----------------------------------------------------
extern "C" void kernel_launch(void* const* d_in, const int* in_sizes, int n_in,
                              void* d_out, int out_size) {
    const float* x    = (const float*)d_in[0];
    const int*   ei   = (const int*)d_in[1];
    const float* Wm   = (const float*)d_in[2];
    const float* bias = (const float*)d_in[3];
    float* out = (float*)d_out;

    int n = in_sizes[0] / 128;   // 50000
    int e = in_sizes[1] / 2;     // 800000
    int n4 = (n + 3) / 4;

    cudaFuncSetAttribute(k_gemm, cudaFuncAttributeMaxDynamicSharedMemorySize, SM_TOTAL);

    k_count<<<(e + 255) / 256, 256>>>(ei, e);
    k_scan<<<1, 1024>>>(n);
    int fh_threads = (n * 32 > e) ? n * 32 : e;
    k_fill_half<<<(fh_threads + 255) / 256, 256>>>(ei, x, Wm, e, n);
    k_agg<<<(n * 32 + 255) / 256, 256>>>(n);          // launch index 3 -> profiled
    k_gemm<<<(n + 127) / 128, 256, SM_TOTAL>>>(bias, out, n);
    k_init<<<(n4 + 255) / 256, 256>>>(n4);            // zero counters for next call
}

// round 9
// speedup vs baseline: 2.6497x; 2.4086x over previous
#include <cuda_runtime.h>
#include <cuda_fp16.h>
#include <cstdint>

#define N_MAX 50000
#define E_MAX 800000
#define NBLK_SCAN 256   // max scan blocks supported (n/256 = 196 here)

// ---------------- scratch (__device__ globals; zero-initialized at load) ----
__device__ int      g_deg_in[N_MAX];     // zeroed by k_init at END of each call
__device__ int      g_deg_out[N_MAX];
__device__ int      g_cursor[N_MAX];
__device__ int      g_row_start[N_MAX + 1];
__device__ int      g_bagg[NBLK_SCAN];
__device__ int      g_csr_src[E_MAX];
__device__ float    g_norm_src[N_MAX];
__device__ uint2    g_h16[(size_t)N_MAX * 32];    // fp16 x*norm_src
__device__ uint2    g_aggh[(size_t)N_MAX * 32];   // fp16 aggregated rows
__device__ uint32_t g_wfrag[8192];                // W in HMMA B-fragment layout

__device__ __forceinline__ void mma_f16(float c[4], uint32_t a0, uint32_t a1,
                                        uint32_t a2, uint32_t a3,
                                        uint32_t b0, uint32_t b1) {
    asm volatile(
        "mma.sync.aligned.m16n8k16.row.col.f32.f16.f16.f32 "
        "{%0,%1,%2,%3}, {%4,%5,%6,%7}, {%8,%9}, {%0,%1,%2,%3};"
        : "+f"(c[0]), "+f"(c[1]), "+f"(c[2]), "+f"(c[3])
        : "r"(a0), "r"(a1), "r"(a2), "r"(a3), "r"(b0), "r"(b1));
}

// ---------------- launch 0: degree count (counters pre-zeroed) --------------
__global__ void k_count(const int* __restrict__ ei, int e) {
    int i = blockIdx.x * blockDim.x + threadIdx.x;
    if (i < e) {
        atomicAdd(&g_deg_out[ei[i]], 1);
        atomicAdd(&g_deg_in[ei[e + i]], 1);
    }
}

// ---------------- launch 1: block aggregates of deg_in + norm_src -----------
__global__ void k_scanA(int n) {
    int t = threadIdx.x;
    int i = blockIdx.x * 256 + t;
    int v = (i < n) ? g_deg_in[i] : 0;
    if (i < n) g_norm_src[i] = rsqrtf(fmaxf((float)g_deg_out[i], 1.0f));
    // warp reduce
    int s = v;
#pragma unroll
    for (int o = 16; o; o >>= 1) s += __shfl_down_sync(0xFFFFFFFFu, s, o);
    __shared__ int ws[8];
    if ((t & 31) == 0) ws[t >> 5] = s;
    __syncthreads();
    if (t == 0) {
        int tot = 0;
#pragma unroll
        for (int w = 0; w < 8; ++w) tot += ws[w];
        g_bagg[blockIdx.x] = tot;
    }
}

// ---------------- launch 2: per-block offsets + local scan -> row_start -----
__global__ void k_scanB(int n) {
    int b = blockIdx.x, t = threadIdx.x;

    // offset = sum of g_bagg[0..b-1]  (parallel reduce; b <= 255)
    __shared__ int red[256];
    red[t] = (t < b) ? g_bagg[t] : 0;
    __syncthreads();
#pragma unroll
    for (int o = 128; o; o >>= 1) {
        if (t < o) red[t] += red[t + o];
        __syncthreads();
    }
    int offset = red[0];

    // intra-block inclusive scan of this block's 256 deg values
    int i = b * 256 + t;
    int d = (i < n) ? g_deg_in[i] : 0;
    int x = d;
#pragma unroll
    for (int o = 1; o < 32; o <<= 1) {
        int y = __shfl_up_sync(0xFFFFFFFFu, x, o);
        if ((t & 31) >= o) x += y;
    }
    __shared__ int wsum[8];
    __shared__ int woff[8];
    if ((t & 31) == 31) wsum[t >> 5] = x;
    __syncthreads();
    if (t == 0) {
        int r = 0;
#pragma unroll
        for (int w = 0; w < 8; ++w) { woff[w] = r; r += wsum[w]; }
    }
    __syncthreads();
    int incl = x + woff[t >> 5];
    int excl = incl - d;
    if (i < n) g_row_start[i] = offset + excl;
    if (i == n - 1) g_row_start[n] = offset + incl;
}

// ---------------- launch 3: CSR fill + fp16 x conversion + W frag conv ------
__global__ void k_fill_half(const int* __restrict__ ei, const float* __restrict__ x,
                            const float* __restrict__ Wm, int e, int n) {
    int i = blockIdx.x * blockDim.x + threadIdx.x;
    if (i < e) {
        int s = ei[i];
        int d = ei[e + i];
        int pos = atomicAdd(&g_cursor[d], 1);
        g_csr_src[g_row_start[d] + pos] = s;
    }
    int cvt_total = n * 32;
    if (i < cvt_total) {
        int node = i >> 5;
        float nm = g_norm_src[node];
        float4 v = reinterpret_cast<const float4*>(x)[i];
        __half2 h0 = __floats2half2_rn(v.x * nm, v.y * nm);
        __half2 h1 = __floats2half2_rn(v.z * nm, v.w * nm);
        uint2 o;
        o.x = *(uint32_t*)&h0;
        o.y = *(uint32_t*)&h1;
        g_h16[i] = o;
    }
    // W -> m16n8k16 B-fragment image: u = (nt*8+ks)*64 + lane*2 + reg
    if (i < 8192) {
        int u = i;
        int reg  = u & 1;
        int lane = (u >> 1) & 31;
        int grp  = u >> 6;              // nt*8+ks
        int ks   = grp & 7;
        int nt   = grp >> 3;
        int nn   = nt * 8 + (lane >> 2);
        int klo  = (lane & 3) * 2 + reg * 8;
        int k    = ks * 16 + klo;
        __half2 h = __floats2half2_rn(Wm[k * 128 + nn], Wm[(k + 1) * 128 + nn]);
        g_wfrag[u] = *(uint32_t*)&h;
    }
}

// ---------------- launch 4: aggregation, warp per node ----------------------
__global__ __launch_bounds__(256)
void k_agg(int n) {
    int warp = (blockIdx.x * blockDim.x + threadIdx.x) >> 5;
    int lane = threadIdx.x & 31;
    if (warp >= n) return;

    int beg = g_row_start[warp];
    int end = g_row_start[warp + 1];
    int deg = end - beg;

    float ax = 0.f, ay = 0.f, az = 0.f, aw = 0.f;

    int idx = beg;
    for (; idx + 4 <= end; idx += 4) {
        int s0 = g_csr_src[idx],     s1 = g_csr_src[idx + 1];
        int s2 = g_csr_src[idx + 2], s3 = g_csr_src[idx + 3];
        uint2 v0 = g_h16[(size_t)s0 * 32 + lane];
        uint2 v1 = g_h16[(size_t)s1 * 32 + lane];
        uint2 v2 = g_h16[(size_t)s2 * 32 + lane];
        uint2 v3 = g_h16[(size_t)s3 * 32 + lane];
        float2 f;
        f = __half22float2(*(__half2*)&v0.x); ax += f.x; ay += f.y;
        f = __half22float2(*(__half2*)&v0.y); az += f.x; aw += f.y;
        f = __half22float2(*(__half2*)&v1.x); ax += f.x; ay += f.y;
        f = __half22float2(*(__half2*)&v1.y); az += f.x; aw += f.y;
        f = __half22float2(*(__half2*)&v2.x); ax += f.x; ay += f.y;
        f = __half22float2(*(__half2*)&v2.y); az += f.x; aw += f.y;
        f = __half22float2(*(__half2*)&v3.x); ax += f.x; ay += f.y;
        f = __half22float2(*(__half2*)&v3.y); az += f.x; aw += f.y;
    }
    for (; idx < end; ++idx) {
        int s0 = g_csr_src[idx];
        uint2 v0 = g_h16[(size_t)s0 * 32 + lane];
        float2 f0 = __half22float2(*(__half2*)&v0.x);
        float2 f1 = __half22float2(*(__half2*)&v0.y);
        ax += f0.x; ay += f0.y; az += f1.x; aw += f1.y;
    }

    float nd = rsqrtf(fmaxf((float)deg, 1.0f));
    __half2 h0 = __floats2half2_rn(ax * nd, ay * nd);
    __half2 h1 = __floats2half2_rn(az * nd, aw * nd);
    uint2 o;
    o.x = *(uint32_t*)&h0;
    o.y = *(uint32_t*)&h1;
    g_aggh[(size_t)warp * 32 + lane] = o;
}

// ---------------- launch 5: GEMM (fp16 HMMA, pre-converted B) ---------------
// smem: bias 512B | A tile 128 x 136 halves (34KB) | B frags 32KB => ~67KB
#define A_PITCH_H 136
#define SM_BIAS   0
#define SM_A      512
#define SM_BF     (512 + 128 * A_PITCH_H * 2)
#define SM_TOTAL  (SM_BF + 16 * 8 * 32 * 8)

__global__ __launch_bounds__(256, 2)
void k_gemm(const float* __restrict__ bias, float* __restrict__ out, int n) {
    extern __shared__ char smem[];
    float*    sBias = (float*)(smem + SM_BIAS);
    __half*   sA    = (__half*)(smem + SM_A);
    uint2*    sBf   = (uint2*)(smem + SM_BF);

    int tid = threadIdx.x;
    int wid = tid >> 5;
    int lid = tid & 31;
    int rowBase = blockIdx.x * 128;

    if (tid < 128) sBias[tid] = bias[tid];

    // stage B fragments: coalesced uint4 copy of pre-converted image (32KB)
#pragma unroll
    for (int i = 0; i < 8; ++i) {
        int u4 = tid + i * 256;
        reinterpret_cast<uint4*>(sBf)[u4] =
            reinterpret_cast<const uint4*>(g_wfrag)[u4];
    }

    // stage A tile coalesced: 128 rows x 128 halves from g_aggh
#pragma unroll
    for (int i = 0; i < 8; ++i) {
        int fid = tid + i * 256;
        int r = fid >> 4;
        int cq = fid & 15;
        int grow = rowBase + r;
        uint4 v = make_uint4(0u, 0u, 0u, 0u);
        if (grow < n)
            v = reinterpret_cast<const uint4*>(&g_aggh[(size_t)grow * 32])[cq];
        *reinterpret_cast<uint4*>(&sA[r * A_PITCH_H + cq * 8]) = v;
    }
    __syncthreads();

    float acc[16][4];
#pragma unroll
    for (int nt = 0; nt < 16; ++nt)
#pragma unroll
        for (int q = 0; q < 4; ++q) acc[nt][q] = 0.f;

    int m0 = wid * 16 + (lid >> 2);
#pragma unroll
    for (int ks = 0; ks < 8; ++ks) {
        int k0 = ks * 16 + (lid & 3) * 2;
        uint32_t a0 = *(const uint32_t*)&sA[m0 * A_PITCH_H + k0];
        uint32_t a1 = *(const uint32_t*)&sA[(m0 + 8) * A_PITCH_H + k0];
        uint32_t a2 = *(const uint32_t*)&sA[m0 * A_PITCH_H + k0 + 8];
        uint32_t a3 = *(const uint32_t*)&sA[(m0 + 8) * A_PITCH_H + k0 + 8];
#pragma unroll
        for (int nt = 0; nt < 16; ++nt) {
            uint2 b = sBf[(nt * 8 + ks) * 32 + lid];
            mma_f16(acc[nt], a0, a1, a2, a3, b.x, b.y);
        }
    }

    int rA = rowBase + m0;
    int rB = rA + 8;
#pragma unroll
    for (int nt = 0; nt < 16; ++nt) {
        int col = nt * 8 + (lid & 3) * 2;
        float b0 = sBias[col], b1 = sBias[col + 1];
        if (rA < n) {
            float2 v;
            v.x = fmaxf(acc[nt][0] + b0, 0.f);
            v.y = fmaxf(acc[nt][1] + b1, 0.f);
            *(float2*)&out[(size_t)rA * 128 + col] = v;
        }
        if (rB < n) {
            float2 v;
            v.x = fmaxf(acc[nt][2] + b0, 0.f);
            v.y = fmaxf(acc[nt][3] + b1, 0.f);
            *(float2*)&out[(size_t)rB * 128 + col] = v;
        }
    }
}

// ---------------- launch 6: zero counters for the NEXT call -----------------
__global__ void k_init(int n4) {
    int i = blockIdx.x * blockDim.x + threadIdx.x;
    int4 z = make_int4(0, 0, 0, 0);
    if (i < n4) {
        reinterpret_cast<int4*>(g_deg_in)[i] = z;
        reinterpret_cast<int4*>(g_deg_out)[i] = z;
        reinterpret_cast<int4*>(g_cursor)[i] = z;
    }
}

// ---------------- launch ----------------------------------------------------
extern "C" void kernel_launch(void* const* d_in, const int* in_sizes, int n_in,
                              void* d_out, int out_size) {
    const float* x    = (const float*)d_in[0];
    const int*   ei   = (const int*)d_in[1];
    const float* Wm   = (const float*)d_in[2];
    const float* bias = (const float*)d_in[3];
    float* out = (float*)d_out;

    int n = in_sizes[0] / 128;   // 50000
    int e = in_sizes[1] / 2;     // 800000
    int n4 = (n + 3) / 4;
    int nblk = (n + 255) / 256;  // 196 <= NBLK_SCAN

    cudaFuncSetAttribute(k_gemm, cudaFuncAttributeMaxDynamicSharedMemorySize, SM_TOTAL);

    k_count<<<(e + 255) / 256, 256>>>(ei, e);
    k_scanA<<<nblk, 256>>>(n);
    k_scanB<<<nblk, 256>>>(n);
    int fh_threads = (n * 32 > e) ? n * 32 : e;
    k_fill_half<<<(fh_threads + 255) / 256, 256>>>(ei, x, Wm, e, n);
    k_agg<<<(n * 32 + 255) / 256, 256>>>(n);
    k_gemm<<<(n + 127) / 128, 256, SM_TOTAL>>>(bias, out, n);
    k_init<<<(n4 + 255) / 256, 256>>>(n4);
}

// round 10
// speedup vs baseline: 2.7319x; 1.0310x over previous
#include <cuda_runtime.h>
#include <cuda_fp16.h>
#include <cstdint>

#define N_MAX 50000
#define E_MAX 800000
#define NBLK_SCAN 256   // max scan blocks supported (n/256 = 196 here)

// ---------------- scratch (__device__ globals; zero-initialized at load) ----
__device__ int      g_deg_in[N_MAX + 2];   // padded to int4 multiple for zeroing
__device__ int      g_deg_out[N_MAX + 2];  // (N_MAX+2 = 50002; zero 12502 int4 > needed)
__device__ int      g_cursor[N_MAX + 2];
__device__ int      g_row_start[N_MAX + 1];
__device__ int      g_bagg[NBLK_SCAN];
__device__ int      g_csr_src[E_MAX];
__device__ float    g_norm_src[N_MAX];
__device__ uint2    g_h16[(size_t)N_MAX * 32];    // fp16 x*norm_src
__device__ uint2    g_aggh[(size_t)N_MAX * 32];   // fp16 aggregated rows
__device__ uint32_t g_wfrag[8192];                // W in HMMA B-fragment layout

__device__ __forceinline__ void mma_f16(float c[4], uint32_t a0, uint32_t a1,
                                        uint32_t a2, uint32_t a3,
                                        uint32_t b0, uint32_t b1) {
    asm volatile(
        "mma.sync.aligned.m16n8k16.row.col.f32.f16.f16.f32 "
        "{%0,%1,%2,%3}, {%4,%5,%6,%7}, {%8,%9}, {%0,%1,%2,%3};"
        : "+f"(c[0]), "+f"(c[1]), "+f"(c[2]), "+f"(c[3])
        : "r"(a0), "r"(a1), "r"(a2), "r"(a3), "r"(b0), "r"(b1));
}

// ---------------- launch 0: degree count (counters pre-zeroed) --------------
__global__ void k_count(const int* __restrict__ ei, int e4, int e) {
    int i = blockIdx.x * blockDim.x + threadIdx.x;
    if (i < e4) {
        int4 s = reinterpret_cast<const int4*>(ei)[i];
        int4 d = reinterpret_cast<const int4*>(ei + e)[i];
        atomicAdd(&g_deg_out[s.x], 1); atomicAdd(&g_deg_out[s.y], 1);
        atomicAdd(&g_deg_out[s.z], 1); atomicAdd(&g_deg_out[s.w], 1);
        atomicAdd(&g_deg_in[d.x], 1);  atomicAdd(&g_deg_in[d.y], 1);
        atomicAdd(&g_deg_in[d.z], 1);  atomicAdd(&g_deg_in[d.w], 1);
    }
}

// ---------------- launch 1: block aggregates of deg_in + norm_src -----------
__global__ void k_scanA(int n) {
    int t = threadIdx.x;
    int i = blockIdx.x * 256 + t;
    int v = (i < n) ? g_deg_in[i] : 0;
    if (i < n) g_norm_src[i] = rsqrtf(fmaxf((float)g_deg_out[i], 1.0f));
    int s = v;
#pragma unroll
    for (int o = 16; o; o >>= 1) s += __shfl_down_sync(0xFFFFFFFFu, s, o);
    __shared__ int ws[8];
    if ((t & 31) == 0) ws[t >> 5] = s;
    __syncthreads();
    if (t == 0) {
        int tot = 0;
#pragma unroll
        for (int w = 0; w < 8; ++w) tot += ws[w];
        g_bagg[blockIdx.x] = tot;
    }
}

// ---------------- launch 2: per-block offsets + local scan -> row_start -----
__global__ void k_scanB(int n) {
    int b = blockIdx.x, t = threadIdx.x;

    __shared__ int red[256];
    red[t] = (t < b) ? g_bagg[t] : 0;
    __syncthreads();
#pragma unroll
    for (int o = 128; o; o >>= 1) {
        if (t < o) red[t] += red[t + o];
        __syncthreads();
    }
    int offset = red[0];

    int i = b * 256 + t;
    int d = (i < n) ? g_deg_in[i] : 0;
    int x = d;
#pragma unroll
    for (int o = 1; o < 32; o <<= 1) {
        int y = __shfl_up_sync(0xFFFFFFFFu, x, o);
        if ((t & 31) >= o) x += y;
    }
    __shared__ int wsum[8];
    __shared__ int woff[8];
    if ((t & 31) == 31) wsum[t >> 5] = x;
    __syncthreads();
    if (t == 0) {
        int r = 0;
#pragma unroll
        for (int w = 0; w < 8; ++w) { woff[w] = r; r += wsum[w]; }
    }
    __syncthreads();
    int incl = x + woff[t >> 5];
    int excl = incl - d;
    if (i < n) g_row_start[i] = offset + excl;
    if (i == n - 1) g_row_start[n] = offset + incl;
}

// ---------------- launch 3: CSR fill (4 edges/thread) + fp16 conv + W frag --
__global__ void k_fill_half(const int* __restrict__ ei, const float* __restrict__ x,
                            const float* __restrict__ Wm, int e4, int e, int n) {
    int i = blockIdx.x * blockDim.x + threadIdx.x;
    if (i < e4) {                       // 4 independent scatter chains -> MLP
        int4 s = reinterpret_cast<const int4*>(ei)[i];
        int4 d = reinterpret_cast<const int4*>(ei + e)[i];
        g_csr_src[g_row_start[d.x] + atomicAdd(&g_cursor[d.x], 1)] = s.x;
        g_csr_src[g_row_start[d.y] + atomicAdd(&g_cursor[d.y], 1)] = s.y;
        g_csr_src[g_row_start[d.z] + atomicAdd(&g_cursor[d.z], 1)] = s.z;
        g_csr_src[g_row_start[d.w] + atomicAdd(&g_cursor[d.w], 1)] = s.w;
    }
    int cvt_total = n * 32;
    if (i < cvt_total) {
        int node = i >> 5;
        float nm = g_norm_src[node];
        float4 v = reinterpret_cast<const float4*>(x)[i];
        __half2 h0 = __floats2half2_rn(v.x * nm, v.y * nm);
        __half2 h1 = __floats2half2_rn(v.z * nm, v.w * nm);
        uint2 o;
        o.x = *(uint32_t*)&h0;
        o.y = *(uint32_t*)&h1;
        g_h16[i] = o;
    }
    // W -> m16n8k16 B-fragment image: u = (nt*8+ks)*64 + lane*2 + reg
    if (i < 8192) {
        int u = i;
        int reg  = u & 1;
        int lane = (u >> 1) & 31;
        int grp  = u >> 6;
        int ks   = grp & 7;
        int nt   = grp >> 3;
        int nn   = nt * 8 + (lane >> 2);
        int klo  = (lane & 3) * 2 + reg * 8;
        int k    = ks * 16 + klo;
        __half2 h = __floats2half2_rn(Wm[k * 128 + nn], Wm[(k + 1) * 128 + nn]);
        g_wfrag[u] = *(uint32_t*)&h;
    }
}

// ---------------- launch 4: aggregation, warp per node, fp16 pair-tree ------
__global__ __launch_bounds__(256)
void k_agg(int n) {
    int warp = (blockIdx.x * blockDim.x + threadIdx.x) >> 5;
    int lane = threadIdx.x & 31;
    if (warp >= n) return;

    int beg = g_row_start[warp];
    int end = g_row_start[warp + 1];
    int deg = end - beg;

    float ax = 0.f, ay = 0.f, az = 0.f, aw = 0.f;

    int idx = beg;
    for (; idx + 4 <= end; idx += 4) {
        int s0 = g_csr_src[idx],     s1 = g_csr_src[idx + 1];
        int s2 = g_csr_src[idx + 2], s3 = g_csr_src[idx + 3];
        uint2 v0 = g_h16[(size_t)s0 * 32 + lane];
        uint2 v1 = g_h16[(size_t)s1 * 32 + lane];
        uint2 v2 = g_h16[(size_t)s2 * 32 + lane];
        uint2 v3 = g_h16[(size_t)s3 * 32 + lane];
        // depth-2 fp16 pairwise tree: 6 HADD2, then 2 cvt + 4 FADD
        __half2 p = __hadd2(__hadd2(*(__half2*)&v0.x, *(__half2*)&v1.x),
                            __hadd2(*(__half2*)&v2.x, *(__half2*)&v3.x));
        __half2 q = __hadd2(__hadd2(*(__half2*)&v0.y, *(__half2*)&v1.y),
                            __hadd2(*(__half2*)&v2.y, *(__half2*)&v3.y));
        float2 fp = __half22float2(p);
        float2 fq = __half22float2(q);
        ax += fp.x; ay += fp.y; az += fq.x; aw += fq.y;
    }
    for (; idx < end; ++idx) {
        int s0 = g_csr_src[idx];
        uint2 v0 = g_h16[(size_t)s0 * 32 + lane];
        float2 f0 = __half22float2(*(__half2*)&v0.x);
        float2 f1 = __half22float2(*(__half2*)&v0.y);
        ax += f0.x; ay += f0.y; az += f1.x; aw += f1.y;
    }

    float nd = rsqrtf(fmaxf((float)deg, 1.0f));
    __half2 h0 = __floats2half2_rn(ax * nd, ay * nd);
    __half2 h1 = __floats2half2_rn(az * nd, aw * nd);
    uint2 o;
    o.x = *(uint32_t*)&h0;
    o.y = *(uint32_t*)&h1;
    g_aggh[(size_t)warp * 32 + lane] = o;
}

// ---------------- launch 5: GEMM + counter re-zero for next call ------------
// smem: bias 512B | A tile 128 x 136 halves (34KB) | B frags 32KB => ~67KB
#define A_PITCH_H 136
#define SM_BIAS   0
#define SM_A      512
#define SM_BF     (512 + 128 * A_PITCH_H * 2)
#define SM_TOTAL  (SM_BF + 16 * 8 * 32 * 8)

__global__ __launch_bounds__(256, 2)
void k_gemm(const float* __restrict__ bias, float* __restrict__ out, int n, int nz4) {
    extern __shared__ char smem[];
    float*    sBias = (float*)(smem + SM_BIAS);
    __half*   sA    = (__half*)(smem + SM_A);
    uint2*    sBf   = (uint2*)(smem + SM_BF);

    int tid = threadIdx.x;
    int wid = tid >> 5;
    int lid = tid & 31;
    int rowBase = blockIdx.x * 128;

    // zero counters for NEXT call (independent of this kernel's data)
    {
        int g = blockIdx.x * 256 + tid;
        int4 z = make_int4(0, 0, 0, 0);
        if (g < nz4)
            reinterpret_cast<int4*>(g_deg_in)[g] = z;
        else if (g < 2 * nz4)
            reinterpret_cast<int4*>(g_deg_out)[g - nz4] = z;
        else if (g < 3 * nz4)
            reinterpret_cast<int4*>(g_cursor)[g - 2 * nz4] = z;
    }

    if (tid < 128) sBias[tid] = bias[tid];

    // stage B fragments: coalesced uint4 copy of pre-converted image (32KB)
#pragma unroll
    for (int i = 0; i < 8; ++i) {
        int u4 = tid + i * 256;
        reinterpret_cast<uint4*>(sBf)[u4] =
            reinterpret_cast<const uint4*>(g_wfrag)[u4];
    }

    // stage A tile coalesced: 128 rows x 128 halves from g_aggh
#pragma unroll
    for (int i = 0; i < 8; ++i) {
        int fid = tid + i * 256;
        int r = fid >> 4;
        int cq = fid & 15;
        int grow = rowBase + r;
        uint4 v = make_uint4(0u, 0u, 0u, 0u);
        if (grow < n)
            v = reinterpret_cast<const uint4*>(&g_aggh[(size_t)grow * 32])[cq];
        *reinterpret_cast<uint4*>(&sA[r * A_PITCH_H + cq * 8]) = v;
    }
    __syncthreads();

    float acc[16][4];
#pragma unroll
    for (int nt = 0; nt < 16; ++nt)
#pragma unroll
        for (int q = 0; q < 4; ++q) acc[nt][q] = 0.f;

    int m0 = wid * 16 + (lid >> 2);
#pragma unroll
    for (int ks = 0; ks < 8; ++ks) {
        int k0 = ks * 16 + (lid & 3) * 2;
        uint32_t a0 = *(const uint32_t*)&sA[m0 * A_PITCH_H + k0];
        uint32_t a1 = *(const uint32_t*)&sA[(m0 + 8) * A_PITCH_H + k0];
        uint32_t a2 = *(const uint32_t*)&sA[m0 * A_PITCH_H + k0 + 8];
        uint32_t a3 = *(const uint32_t*)&sA[(m0 + 8) * A_PITCH_H + k0 + 8];
#pragma unroll
        for (int nt = 0; nt < 16; ++nt) {
            uint2 b = sBf[(nt * 8 + ks) * 32 + lid];
            mma_f16(acc[nt], a0, a1, a2, a3, b.x, b.y);
        }
    }

    int rA = rowBase + m0;
    int rB = rA + 8;
#pragma unroll
    for (int nt = 0; nt < 16; ++nt) {
        int col = nt * 8 + (lid & 3) * 2;
        float b0 = sBias[col], b1 = sBias[col + 1];
        if (rA < n) {
            float2 v;
            v.x = fmaxf(acc[nt][0] + b0, 0.f);
            v.y = fmaxf(acc[nt][1] + b1, 0.f);
            *(float2*)&out[(size_t)rA * 128 + col] = v;
        }
        if (rB < n) {
            float2 v;
            v.x = fmaxf(acc[nt][2] + b0, 0.f);
            v.y = fmaxf(acc[nt][3] + b1, 0.f);
            *(float2*)&out[(size_t)rB * 128 + col] = v;
        }
    }
}

// ---------------- launch ----------------------------------------------------
extern "C" void kernel_launch(void* const* d_in, const int* in_sizes, int n_in,
                              void* d_out, int out_size) {
    const float* x    = (const float*)d_in[0];
    const int*   ei   = (const int*)d_in[1];
    const float* Wm   = (const float*)d_in[2];
    const float* bias = (const float*)d_in[3];
    float* out = (float*)d_out;

    int n = in_sizes[0] / 128;   // 50000
    int e = in_sizes[1] / 2;     // 800000
    int e4 = e / 4;
    int nz4 = (n + 3) / 4;       // int4 chunks per counter array
    int nblk = (n + 255) / 256;  // 196 <= NBLK_SCAN

    cudaFuncSetAttribute(k_gemm, cudaFuncAttributeMaxDynamicSharedMemorySize, SM_TOTAL);

    k_count<<<(e4 + 255) / 256, 256>>>(ei, e4, e);
    k_scanA<<<nblk, 256>>>(n);
    k_scanB<<<nblk, 256>>>(n);
    int fh_threads = (n * 32 > e4) ? n * 32 : e4;
    k_fill_half<<<(fh_threads + 255) / 256, 256>>>(ei, x, Wm, e4, e, n);
    k_agg<<<(n * 32 + 255) / 256, 256>>>(n);
    k_gemm<<<(n + 127) / 128, 256, SM_TOTAL>>>(bias, out, n, nz4);
}